// round 13
// baseline (speedup 1.0000x reference)
#include <cuda_runtime.h>
#include <cuda_fp16.h>
#include <math.h>

#define WW 512
#define HH 512
#define NIMG 8
#define HWSZ (HH * WW)
#define NPLANES 16            // 2 streams (p, target) x 8 samples
#define TOTALSZ (NPLANES * HWSZ)
#define NITER 50

#define STRIPS 5              // 5 strips x 120 output cols (lanes 1..30 of 4-col lanes)
#define CHUNK_ROWS 8
#define CHUNKS 64             // 512 / 8
#define WARPS_TOTAL (STRIPS * CHUNKS * NPLANES)   // 5120

#define SWEEP_BLOCK 256
#define SWEEP_GRID (WARPS_TOTAL / (SWEEP_BLOCK / 32))  // 640

#define IT2_BLOCK 128
#define IT2_GRID (WARPS_TOTAL / (IT2_BLOCK / 32))      // 1280

// Static scratch (no allocations allowed in kernel_launch)
__device__ float  g_p[NIMG * HWSZ];    // sigmoid(output) fp32, for the Dice-side reduction
__device__ __half g_imgA[TOTALSZ];     // ping (fp16)
__device__ __half g_imgB[TOTALSZ];     // pong (fp16)
__device__ __half g_skel[TOTALSZ];     // skeleton accumulators (fp16)
__device__ double g_sums[NIMG][7];     // per-sample reduction accumulators

// ---------------------------------------------------------------------------
// fp16x4 helpers: one lane owns 4 adjacent columns as {lo=(c0,c1), hi=(c2,c3)}
// ---------------------------------------------------------------------------
struct __align__(8) H4 { __half2 lo, hi; };

__device__ __forceinline__ __half h_inf()  { return __ushort_as_half((unsigned short)0x7C00); }
__device__ __forceinline__ __half h_ninf() { return __ushort_as_half((unsigned short)0xFC00); }
__device__ __forceinline__ H4 h4fill(__half v) { __half2 p = __half2half2(v); H4 r; r.lo = p; r.hi = p; return r; }
__device__ __forceinline__ H4 h4_inf()  { return h4fill(h_inf()); }
__device__ __forceinline__ H4 h4_ninf() { return h4fill(h_ninf()); }
__device__ __forceinline__ H4 h4_zero() { return h4fill(__ushort_as_half(0)); }

__device__ __forceinline__ H4 min_h(H4 a, H4 b) { H4 r; r.lo = __hmin2(a.lo, b.lo); r.hi = __hmin2(a.hi, b.hi); return r; }
__device__ __forceinline__ H4 max_h(H4 a, H4 b) { H4 r; r.lo = __hmax2(a.lo, b.lo); r.hi = __hmax2(a.hi, b.hi); return r; }
__device__ __forceinline__ H4 vmin3h(H4 a, H4 b, H4 c) { return min_h(min_h(a, b), c); }
__device__ __forceinline__ H4 vmax3h(H4 a, H4 b, H4 c) { return max_h(max_h(a, b), c); }

// horizontal 3-tap min across the warp-wide row
__device__ __forceinline__ H4 hmin3h(H4 v, int lane) {
    __half2 fl = __shfl_up_sync(0xffffffffu, v.hi, 1);
    __half2 fr = __shfl_down_sync(0xffffffffu, v.lo, 1);
    __half L = (lane == 0)  ? h_inf() : __high2half(fl);
    __half R = (lane == 31) ? h_inf() : __low2half(fr);
    __half2 La = __halves2half2(L, __low2half(v.lo));                   // {L, a}
    __half2 bc = __halves2half2(__high2half(v.lo), __low2half(v.hi));   // {b, c}
    __half2 dR = __halves2half2(__high2half(v.hi), R);                  // {d, R}
    H4 o;
    o.lo = __hmin2(__hmin2(La, v.lo), bc);   // {min(L,a,b), min(a,b,c)}
    o.hi = __hmin2(__hmin2(bc, v.hi), dR);   // {min(b,c,d), min(c,d,R)}
    return o;
}
__device__ __forceinline__ H4 hmax3h(H4 v, int lane) {
    __half2 fl = __shfl_up_sync(0xffffffffu, v.hi, 1);
    __half2 fr = __shfl_down_sync(0xffffffffu, v.lo, 1);
    __half L = (lane == 0)  ? h_ninf() : __high2half(fl);
    __half R = (lane == 31) ? h_ninf() : __low2half(fr);
    __half2 La = __halves2half2(L, __low2half(v.lo));
    __half2 bc = __halves2half2(__high2half(v.lo), __low2half(v.hi));
    __half2 dR = __halves2half2(__high2half(v.hi), R);
    H4 o;
    o.lo = __hmax2(__hmax2(La, v.lo), bc);
    o.hi = __hmax2(__hmax2(bc, v.hi), dR);
    return o;
}
__device__ __forceinline__ H4 relu_subh(H4 a, H4 b) {
    __half2 z = __half2half2(__ushort_as_half(0));
    H4 r;
    r.lo = __hmax2(__hsub2(a.lo, b.lo), z);
    r.hi = __hmax2(__hsub2(a.hi, b.hi), z);
    return r;
}
__device__ __forceinline__ H4 selneg(H4 v, bool ok) { return ok ? v : h4_ninf(); }
// s += relu(d - s*d)
__device__ __forceinline__ void skel_updh(H4& s, H4 d) {
    s.lo = __hadd2(s.lo, __hfma2_relu(__hneg2(s.lo), d.lo, d.lo));
    s.hi = __hadd2(s.hi, __hfma2_relu(__hneg2(s.hi), d.hi, d.hi));
}

// ---------------------------------------------------------------------------
// Init: p = sigmoid(output); g_p fp32; imgA[stream0]=half(p), imgA[stream1]=half(target)
// ---------------------------------------------------------------------------
__global__ void k_init(const float4* __restrict__ out, const float4* __restrict__ tgt) {
    int i = blockIdx.x * blockDim.x + threadIdx.x;
    int stride = gridDim.x * blockDim.x;
    float4* gp = (float4*)g_p;
    H4* ga = (H4*)g_imgA;
    H4* gb = (H4*)(g_imgA + NIMG * HWSZ);
    const int n4 = NIMG * HWSZ / 4;
    for (; i < n4; i += stride) {
        float4 o = out[i];
        float4 v;
        v.x = 1.0f / (1.0f + expf(-o.x));
        v.y = 1.0f / (1.0f + expf(-o.y));
        v.z = 1.0f / (1.0f + expf(-o.z));
        v.w = 1.0f / (1.0f + expf(-o.w));
        gp[i] = v;
        H4 hv; hv.lo = __floats2half2_rn(v.x, v.y); hv.hi = __floats2half2_rn(v.z, v.w);
        ga[i] = hv;
        float4 t = tgt[i];
        H4 ht; ht.lo = __floats2half2_rn(t.x, t.y); ht.hi = __floats2half2_rn(t.z, t.w);
        gb[i] = ht;
    }
}

// ---------------------------------------------------------------------------
// Warp-sweep open-init:  skel = relu(img - dilate(erode(img)))   (fp16)
// 10 steps per 8-row chunk.
// ---------------------------------------------------------------------------
__global__ void __launch_bounds__(SWEEP_BLOCK, 4) k_open_init() {
    const int lane = threadIdx.x & 31;
    const int gw = (blockIdx.x * SWEEP_BLOCK + threadIdx.x) >> 5;
    const int strip = gw % STRIPS;
    const int t = gw / STRIPS;
    const int chunk = t & (CHUNKS - 1);
    const int z = t / CHUNKS;

    const __half* __restrict__ src = g_imgA + z * HWSZ;
    __half* __restrict__ skel = g_skel + z * HWSZ;

    const int c0 = strip * 120 - 4 + 4 * lane;
    const bool colok = (c0 >= 0) && (c0 < WW);
    const bool stok = (lane >= 1) && (lane <= 30) && (c0 < WW);
    const int r0 = chunk * CHUNK_ROWS;
    const int ylim = r0 + 2;

    int y = r0 - 2;
    const __half* srcp = src + y * WW + c0;
    __half* const skb = skel + c0;

    H4 ia = h4_inf(), ib = h4_inf(), ic;
    H4 ha = h4_ninf(), hb = h4_ninf(), hc;

#define OPEN_STEP(IA, IB, IC, HA, HB, HC)                                      \
    {                                                                          \
        bool ldok = colok && ((unsigned)y < (unsigned)HH);                     \
        IC = ldok ? *(const H4*)srcp : h4_inf();                               \
        H4 e1_ = min_h(vmin3h(IA, IB, IC), hmin3h(IB, lane));                  \
        if (!colok || (unsigned)(y - 1) >= (unsigned)HH) e1_ = h4_ninf();      \
        HC = hmax3h(e1_, lane);                                                \
        if (y >= ylim) {                                                       \
            H4 d_ = vmax3h(HA, HB, HC);                                        \
            if (stok) {                                                        \
                H4 o_ = relu_subh(IA, d_);                                     \
                *(H4*)(skb + (y - 2) * WW) = o_;                               \
            }                                                                  \
        }                                                                      \
        ++y;                                                                   \
        srcp += WW;                                                            \
    }

    // 10 steps = 3 groups of 3 + 1
#pragma unroll 1
    for (int k = 0; k < 3; ++k) {
        OPEN_STEP(ia, ib, ic, ha, hb, hc);
        OPEN_STEP(ib, ic, ia, hb, hc, ha);
        OPEN_STEP(ic, ia, ib, hc, ha, hb);
    }
    OPEN_STEP(ia, ib, ic, ha, hb, hc);
#undef OPEN_STEP
}

// ---------------------------------------------------------------------------
// Fused TWO skeleton iterations, fp16 lanes (4 cols/lane), 8-row chunks:
//   E1 = erode(img); E2 = erode(E1) -> new img; E3 = erode(E2)
//   delta1 = relu(E1 - dilate(E2)); delta2 = relu(E2 - dilate(E3))
//   skel row: one load, both updates in-register, one store.
// 16 steps per chunk. Vertical/horizontal halo 4.
// ---------------------------------------------------------------------------
__global__ void __launch_bounds__(IT2_BLOCK, 8) k_iter2(int flip) {
    const int lane = threadIdx.x & 31;
    const int gw = (blockIdx.x * IT2_BLOCK + threadIdx.x) >> 5;
    const int strip = gw % STRIPS;
    const int t = gw / STRIPS;
    const int chunk = t & (CHUNKS - 1);
    const int z = t / CHUNKS;

    const __half* __restrict__ src = (flip ? g_imgB : g_imgA) + z * HWSZ;
    __half* __restrict__ dst = (flip ? g_imgA : g_imgB) + z * HWSZ;
    __half* __restrict__ skel = g_skel + z * HWSZ;

    const int c0 = strip * 120 - 4 + 4 * lane;
    const bool colok = (c0 >= 0) && (c0 < WW);
    const bool stok = (lane >= 1) && (lane <= 30) && (c0 < WW);
    const int r0 = chunk * CHUNK_ROWS;
    const int yD1 = r0 + 3;    // first step producing delta1 (row y-3)
    const int yOUT = r0 + 4;   // first step producing output (row y-4)

    int y = r0 - 4;
    H4 pf;
    {
        bool ldok = colok && ((unsigned)y < (unsigned)HH);
        pf = ldok ? *(const H4*)(src + y * WW + c0) : h4_inf();
    }
    const __half* srcp = src + (y + 1) * WW + c0;
    __half* const skb = skel + c0;
    __half* const dsb = dst + c0;

    H4 ia = h4_inf(), ib = h4_inf(), ic;        // I ring
    H4 ea = h4_inf(), eb = h4_inf(), ec;        // E1 ring
    H4 fa = h4_inf(), fb = h4_inf(), fc;        // E2 ring
    H4 ha = h4_ninf(), hb = h4_ninf(), hc;      // H = hmax(E2)
    H4 ba = h4_ninf(), bb = h4_ninf(), bc;      // Hb = hmax(E3)
    H4 dprev = h4_zero();                       // delta1[y-4]
    H4 spf = h4_zero();                         // skel prefetch

#define STEP2(IA, IB, IC, EA, EB, EC, FA, FB, FC, HA, HB, HC, BA, BB, BC)      \
    {                                                                          \
        H4 icur = pf;                                                          \
        {                                                                      \
            bool ldok = colok && ((unsigned)(y + 1) < (unsigned)HH);           \
            pf = ldok ? *(const H4*)srcp : h4_inf();                           \
            srcp += WW;                                                        \
        }                                                                      \
        IC = icur;                                                             \
        EC = min_h(vmin3h(IA, IB, IC), hmin3h(IB, lane));    /* E1[y-1] */     \
        FC = min_h(vmin3h(EA, EB, EC), hmin3h(EB, lane));    /* E2[y-2] */     \
        HC = hmax3h(selneg(FC, colok && (unsigned)(y - 2) < (unsigned)HH),     \
                    lane);                                                     \
        H4 e3_ = min_h(vmin3h(FA, FB, FC), hmin3h(FB, lane)); /* E3[y-3] */    \
        BC = hmax3h(selneg(e3_, colok && (unsigned)(y - 3) < (unsigned)HH),    \
                    lane);                                                     \
        if (y >= yOUT) {                                     /* row y-4 */     \
            H4 D2 = vmax3h(BA, BB, BC);                                        \
            if (stok) {                                                        \
                H4 d2 = relu_subh(FA, D2);                   /* E2[y-4] */     \
                H4 s = spf;                                                    \
                skel_updh(s, dprev);                                           \
                skel_updh(s, d2);                                              \
                *(H4*)(skb + (y - 4) * WW) = s;                                \
                *(H4*)(dsb + (y - 4) * WW) = FA;                               \
            }                                                                  \
        }                                                                      \
        if (y >= yD1) {                                      /* delta1 y-3 */  \
            H4 D1 = vmax3h(HA, HB, HC);                                        \
            dprev = relu_subh(EA, D1);                       /* E1[y-3] */     \
            if (stok && (unsigned)(y - 3) < (unsigned)HH)                      \
                spf = *(const H4*)(skb + (y - 3) * WW);                        \
        }                                                                      \
        ++y;                                                                   \
    }

    // 16 steps = 5 groups of 3 + 1 (ring rotation by argument permutation)
#pragma unroll 1
    for (int k = 0; k < 5; ++k) {
        STEP2(ia, ib, ic, ea, eb, ec, fa, fb, fc, ha, hb, hc, ba, bb, bc);
        STEP2(ib, ic, ia, eb, ec, ea, fb, fc, fa, hb, hc, ha, bb, bc, ba);
        STEP2(ic, ia, ib, ec, ea, eb, fc, fa, fb, hc, ha, hb, bc, ba, bb);
    }
    STEP2(ia, ib, ic, ea, eb, ec, fa, fb, fc, ha, hb, hc, ba, bb, bc);
#undef STEP2
}

// ---------------------------------------------------------------------------
// Reductions
// ---------------------------------------------------------------------------
__global__ void k_zero() {
    int t = threadIdx.x;
    if (t < NIMG * 7) ((double*)g_sums)[t] = 0.0;
}

__global__ void k_reduce(const float* __restrict__ tgt) {
    const int n = blockIdx.y;
    const H4* __restrict__ sp = (const H4*)(g_skel + n * HWSZ);
    const H4* __restrict__ sl = (const H4*)(g_skel + (NIMG + n) * HWSZ);
    const float4* __restrict__ pp = (const float4*)(g_p + n * HWSZ);
    const float4* __restrict__ tt = (const float4*)(tgt + n * HWSZ);
    const int n4 = HWSZ / 4;

    double a0 = 0, a1 = 0, a2 = 0, a3 = 0, a4 = 0, a5 = 0, a6 = 0;
    for (int i = blockIdx.x * blockDim.x + threadIdx.x; i < n4;
         i += gridDim.x * blockDim.x) {
        H4 s1h = sp[i], s2h = sl[i];
        float2 s1lo = __half22float2(s1h.lo), s1hi = __half22float2(s1h.hi);
        float2 s2lo = __half22float2(s2h.lo), s2hi = __half22float2(s2h.hi);
        float4 pv = pp[i], tv = tt[i];
        a0 += (double)(s1lo.x * tv.x + s1lo.y * tv.y + s1hi.x * tv.z + s1hi.y * tv.w);
        a1 += (double)(s1lo.x + s1lo.y + s1hi.x + s1hi.y);
        a2 += (double)(s2lo.x * pv.x + s2lo.y * pv.y + s2hi.x * pv.z + s2hi.y * pv.w);
        a3 += (double)(s2lo.x + s2lo.y + s2hi.x + s2hi.y);
        a4 += (double)(pv.x * tv.x + pv.y * tv.y + pv.z * tv.z + pv.w * tv.w);
        a5 += (double)(pv.x + pv.y + pv.z + pv.w);
        a6 += (double)(tv.x + tv.y + tv.z + tv.w);
    }
#pragma unroll
    for (int o = 16; o > 0; o >>= 1) {
        a0 += __shfl_down_sync(0xffffffffu, a0, o);
        a1 += __shfl_down_sync(0xffffffffu, a1, o);
        a2 += __shfl_down_sync(0xffffffffu, a2, o);
        a3 += __shfl_down_sync(0xffffffffu, a3, o);
        a4 += __shfl_down_sync(0xffffffffu, a4, o);
        a5 += __shfl_down_sync(0xffffffffu, a5, o);
        a6 += __shfl_down_sync(0xffffffffu, a6, o);
    }
    if ((threadIdx.x & 31) == 0) {
        atomicAdd(&g_sums[n][0], a0);
        atomicAdd(&g_sums[n][1], a1);
        atomicAdd(&g_sums[n][2], a2);
        atomicAdd(&g_sums[n][3], a3);
        atomicAdd(&g_sums[n][4], a4);
        atomicAdd(&g_sums[n][5], a5);
        atomicAdd(&g_sums[n][6], a6);
    }
}

__global__ void k_final(float* __restrict__ out, int out_size) {
    if (threadIdx.x == 0 && blockIdx.x == 0) {
        const double smooth = 1.0;
        double cl = 0.0, dice = 0.0;
        for (int n = 0; n < NIMG; n++) {
            double A = g_sums[n][0], B = g_sums[n][1], C = g_sums[n][2],
                   D = g_sums[n][3], E = g_sums[n][4], F = g_sums[n][5],
                   G = g_sums[n][6];
            double tprec = (A + smooth) / (B + smooth);
            double tsens = (C + smooth) / (D + smooth);
            cl += 1.0 - 2.0 * tprec * tsens / (tprec + tsens);
            dice += 1.0 - 2.0 * (E + smooth) / (F + G + smooth);
        }
        cl /= NIMG;
        dice /= NIMG;
        float loss = (float)(0.7 * dice + 0.3 * cl);
        for (int i = 0; i < out_size; i++) out[i] = loss;
    }
}

// ---------------------------------------------------------------------------
extern "C" void kernel_launch(void* const* d_in, const int* in_sizes, int n_in,
                              void* d_out, int out_size) {
    const float* output = (const float*)d_in[0];
    const float* target = (const float*)d_in[1];
    float* out = (float*)d_out;

    k_init<<<1024, 256>>>((const float4*)output, (const float4*)target);

    k_open_init<<<SWEEP_GRID, SWEEP_BLOCK>>>();

    // 50 iterations = 25 fused-2 launches
    for (int j = 0; j < NITER / 2; ++j) {
        k_iter2<<<IT2_GRID, IT2_BLOCK>>>(j & 1);
    }

    k_zero<<<1, 64>>>();
    k_reduce<<<dim3(32, NIMG), 256>>>(target);
    k_final<<<1, 32>>>(out, out_size);
}

// round 14
// speedup vs baseline: 1.0614x; 1.0614x over previous
#include <cuda_runtime.h>
#include <cuda_fp16.h>
#include <math.h>

#define WW 512
#define HH 512
#define NIMG 8
#define HWSZ (HH * WW)
#define NPLANES 16            // 2 streams (p, target) x 8 samples
#define TOTALSZ (NPLANES * HWSZ)
#define NITER 50

#define STRIPS 5              // 5 strips x 120 output cols (lanes 1..30 of 4-col lanes)
#define CHUNK_ROWS 16
#define CHUNKS 32             // 512 / 16
#define WARPS_TOTAL (STRIPS * CHUNKS * NPLANES)   // 2560

#define SWEEP_BLOCK 256
#define SWEEP_GRID (WARPS_TOTAL / (SWEEP_BLOCK / 32))  // 320

#define IT2_BLOCK 128
#define IT2_GRID (WARPS_TOTAL / (IT2_BLOCK / 32))      // 640

// Static scratch (no allocations allowed in kernel_launch)
__device__ float  g_p[NIMG * HWSZ];    // sigmoid(output) fp32, for the Dice-side reduction
__device__ __half g_imgA[TOTALSZ];     // ping (fp16)
__device__ __half g_imgB[TOTALSZ];     // pong (fp16)
__device__ __half g_skel[TOTALSZ];     // skeleton accumulators (fp16)
__device__ double g_sums[NIMG][7];     // per-sample reduction accumulators

// ---------------------------------------------------------------------------
// fp16x4 helpers: one lane owns 4 adjacent columns as {lo=(c0,c1), hi=(c2,c3)}
// ---------------------------------------------------------------------------
struct __align__(8) H4 { __half2 lo, hi; };

__device__ __forceinline__ __half h_inf()  { return __ushort_as_half((unsigned short)0x7C00); }
__device__ __forceinline__ __half h_ninf() { return __ushort_as_half((unsigned short)0xFC00); }
__device__ __forceinline__ H4 h4fill(__half v) { __half2 p = __half2half2(v); H4 r; r.lo = p; r.hi = p; return r; }
__device__ __forceinline__ H4 h4_inf()  { return h4fill(h_inf()); }
__device__ __forceinline__ H4 h4_ninf() { return h4fill(h_ninf()); }
__device__ __forceinline__ H4 h4_zero() { return h4fill(__ushort_as_half(0)); }

__device__ __forceinline__ H4 min_h(H4 a, H4 b) { H4 r; r.lo = __hmin2(a.lo, b.lo); r.hi = __hmin2(a.hi, b.hi); return r; }
__device__ __forceinline__ H4 max_h(H4 a, H4 b) { H4 r; r.lo = __hmax2(a.lo, b.lo); r.hi = __hmax2(a.hi, b.hi); return r; }
__device__ __forceinline__ H4 vmin3h(H4 a, H4 b, H4 c) { return min_h(min_h(a, b), c); }
__device__ __forceinline__ H4 vmax3h(H4 a, H4 b, H4 c) { return max_h(max_h(a, b), c); }

// horizontal combine with EXPLICIT edge values (no shuffle inside)
__device__ __forceinline__ H4 comb_minh(H4 v, __half L, __half R, int lane) {
    if (lane == 0)  L = h_inf();
    if (lane == 31) R = h_inf();
    __half2 La = __halves2half2(L, __low2half(v.lo));
    __half2 bc = __halves2half2(__high2half(v.lo), __low2half(v.hi));
    __half2 dR = __halves2half2(__high2half(v.hi), R);
    H4 o;
    o.lo = __hmin2(__hmin2(La, v.lo), bc);
    o.hi = __hmin2(__hmin2(bc, v.hi), dR);
    return o;
}
__device__ __forceinline__ H4 comb_maxh(H4 v, __half L, __half R, int lane) {
    if (lane == 0)  L = h_ninf();
    if (lane == 31) R = h_ninf();
    __half2 La = __halves2half2(L, __low2half(v.lo));
    __half2 bc = __halves2half2(__high2half(v.lo), __low2half(v.hi));
    __half2 dR = __halves2half2(__high2half(v.hi), R);
    H4 o;
    o.lo = __hmax2(__hmax2(La, v.lo), bc);
    o.hi = __hmax2(__hmax2(bc, v.hi), dR);
    return o;
}
// classic same-step variants
__device__ __forceinline__ H4 hmin3h(H4 v, int lane) {
    __half2 fl = __shfl_up_sync(0xffffffffu, v.hi, 1);
    __half2 fr = __shfl_down_sync(0xffffffffu, v.lo, 1);
    return comb_minh(v, __high2half(fl), __low2half(fr), lane);
}
__device__ __forceinline__ H4 hmax3h(H4 v, int lane) {
    __half2 fl = __shfl_up_sync(0xffffffffu, v.hi, 1);
    __half2 fr = __shfl_down_sync(0xffffffffu, v.lo, 1);
    return comb_maxh(v, __high2half(fl), __low2half(fr), lane);
}
__device__ __forceinline__ H4 relu_subh(H4 a, H4 b) {
    __half2 z = __half2half2(__ushort_as_half(0));
    H4 r;
    r.lo = __hmax2(__hsub2(a.lo, b.lo), z);
    r.hi = __hmax2(__hsub2(a.hi, b.hi), z);
    return r;
}
__device__ __forceinline__ H4 selneg(H4 v, bool ok) { return ok ? v : h4_ninf(); }
// s += relu(d - s*d)
__device__ __forceinline__ void skel_updh(H4& s, H4 d) {
    s.lo = __hadd2(s.lo, __hfma2_relu(__hneg2(s.lo), d.lo, d.lo));
    s.hi = __hadd2(s.hi, __hfma2_relu(__hneg2(s.hi), d.hi, d.hi));
}

// ---------------------------------------------------------------------------
// Init: p = sigmoid(output); g_p fp32; imgA[stream0]=half(p), imgA[stream1]=half(target)
// ---------------------------------------------------------------------------
__global__ void k_init(const float4* __restrict__ out, const float4* __restrict__ tgt) {
    int i = blockIdx.x * blockDim.x + threadIdx.x;
    int stride = gridDim.x * blockDim.x;
    float4* gp = (float4*)g_p;
    H4* ga = (H4*)g_imgA;
    H4* gb = (H4*)(g_imgA + NIMG * HWSZ);
    const int n4 = NIMG * HWSZ / 4;
    for (; i < n4; i += stride) {
        float4 o = out[i];
        float4 v;
        v.x = 1.0f / (1.0f + expf(-o.x));
        v.y = 1.0f / (1.0f + expf(-o.y));
        v.z = 1.0f / (1.0f + expf(-o.z));
        v.w = 1.0f / (1.0f + expf(-o.w));
        gp[i] = v;
        H4 hv; hv.lo = __floats2half2_rn(v.x, v.y); hv.hi = __floats2half2_rn(v.z, v.w);
        ga[i] = hv;
        float4 t = tgt[i];
        H4 ht; ht.lo = __floats2half2_rn(t.x, t.y); ht.hi = __floats2half2_rn(t.z, t.w);
        gb[i] = ht;
    }
}

// ---------------------------------------------------------------------------
// Warp-sweep open-init:  skel = relu(img - dilate(erode(img)))   (fp16)
// ---------------------------------------------------------------------------
__global__ void __launch_bounds__(SWEEP_BLOCK, 3) k_open_init() {
    const int lane = threadIdx.x & 31;
    const int gw = (blockIdx.x * SWEEP_BLOCK + threadIdx.x) >> 5;
    const int strip = gw % STRIPS;
    const int t = gw / STRIPS;
    const int chunk = t & (CHUNKS - 1);
    const int z = t / CHUNKS;

    const __half* __restrict__ src = g_imgA + z * HWSZ;
    __half* __restrict__ skel = g_skel + z * HWSZ;

    const int c0 = strip * 120 - 4 + 4 * lane;
    const bool colok = (c0 >= 0) && (c0 < WW);
    const bool stok = (lane >= 1) && (lane <= 30) && (c0 < WW);
    const int r0 = chunk * CHUNK_ROWS;
    const int ylim = r0 + 2;

    int y = r0 - 2;
    const __half* srcp = src + y * WW + c0;
    __half* const skb = skel + c0;

    H4 ia = h4_inf(), ib = h4_inf(), ic;
    H4 ha = h4_ninf(), hb = h4_ninf(), hc;

#define OPEN_STEP(IA, IB, IC, HA, HB, HC)                                      \
    {                                                                          \
        bool ldok = colok && ((unsigned)y < (unsigned)HH);                     \
        IC = ldok ? *(const H4*)srcp : h4_inf();                               \
        H4 e1_ = min_h(vmin3h(IA, IB, IC), hmin3h(IB, lane));                  \
        if (!colok || (unsigned)(y - 1) >= (unsigned)HH) e1_ = h4_ninf();      \
        HC = hmax3h(e1_, lane);                                                \
        if (y >= ylim) {                                                       \
            H4 d_ = vmax3h(HA, HB, HC);                                        \
            if (stok) {                                                        \
                H4 o_ = relu_subh(IA, d_);                                     \
                *(H4*)(skb + (y - 2) * WW) = o_;                               \
            }                                                                  \
        }                                                                      \
        ++y;                                                                   \
        srcp += WW;                                                            \
    }

#pragma unroll 1
    for (int k = 0; k < 6; ++k) {
        OPEN_STEP(ia, ib, ic, ha, hb, hc);
        OPEN_STEP(ib, ic, ia, hb, hc, ha);
        OPEN_STEP(ic, ia, ib, hc, ha, hb);
    }
    OPEN_STEP(ia, ib, ic, ha, hb, hc);
    OPEN_STEP(ib, ic, ia, hb, hc, ha);
#undef OPEN_STEP
}

// ---------------------------------------------------------------------------
// Fused TWO skeleton iterations, fp16 lanes. Interior template pre-shuffles
// all stage-row edges one step ahead (SHFL latency off the recurrence path;
// F-row edges shared between hmax-H and next step's hmin-E3: 8 SHFL/step).
// Boundary template is the proven masked version.
// ---------------------------------------------------------------------------
template<bool IN>
__device__ __forceinline__ void it2_body(
    const __half* __restrict__ src, __half* __restrict__ dst,
    __half* __restrict__ skel, const int lane, const int c0, const int r0)
{
    const bool colok = IN || ((c0 >= 0) && (c0 < WW));
    const bool stok = (lane >= 1) && (lane <= 30) && (IN || (c0 < WW));
    const int yD1 = r0 + 3;
    const int yOUT = r0 + 4;

    int y = r0 - 4;
    H4 pf;
    {
        bool ldok = colok && (IN || (unsigned)y < (unsigned)HH);
        pf = ldok ? *(const H4*)(src + y * WW + c0) : h4_inf();
    }
    const __half* srcp = src + (y + 1) * WW + c0;
    __half* const skb = skel + c0;
    __half* const dsb = dst + c0;

    H4 ia = h4_inf(), ib = h4_inf(), ic;        // I ring
    H4 ea = h4_inf(), eb = h4_inf(), ec;        // E1 ring
    H4 fa = h4_inf(), fb = h4_inf(), fc;        // E2 ring
    H4 ha = h4_ninf(), hb = h4_ninf(), hc;      // H = hmax(E2)
    H4 ba = h4_ninf(), bb = h4_ninf(), bc;      // Hb = hmax(E3)
    H4 dprev = h4_zero();                       // delta1[y-4]
    H4 spf = h4_zero();                         // skel prefetch
    // saved edges (interior path): of I row y-1, E1 row y-2, F row y-3
    __half iL = h_inf(), iR = h_inf();
    __half eL = h_inf(), eR = h_inf();
    __half fLo = h_inf(), fRo = h_inf();

#define STEP2(IA, IB, IC, EA, EB, EC, FA, FB, FC, HA, HB, HC, BA, BB, BC)      \
    {                                                                          \
        H4 icur = pf;                                                          \
        if (IN) {                                                              \
            pf = *(const H4*)srcp;                                             \
            srcp += WW;                                                        \
            IC = icur;                                                         \
            /* E1[y-1]: edges of I[y-1] saved last step */                     \
            EC = min_h(vmin3h(IA, IB, IC), comb_minh(IB, iL, iR, lane));       \
            {                                                                  \
                __half2 s1 = __shfl_up_sync(0xffffffffu, icur.hi, 1);          \
                __half2 s2 = __shfl_down_sync(0xffffffffu, icur.lo, 1);        \
                iL = __high2half(s1); iR = __low2half(s2);                     \
            }                                                                  \
            /* E2[y-2]: edges of E1[y-2] saved last step */                    \
            FC = min_h(vmin3h(EA, EB, EC), comb_minh(EB, eL, eR, lane));       \
            {                                                                  \
                __half2 s1 = __shfl_up_sync(0xffffffffu, EC.hi, 1);            \
                __half2 s2 = __shfl_down_sync(0xffffffffu, EC.lo, 1);          \
                eL = __high2half(s1); eR = __low2half(s2);                     \
            }                                                                  \
            /* F[y-2] edges: used for hmax now AND hmin (E3) next step */      \
            __half fLn, fRn;                                                   \
            {                                                                  \
                __half2 s1 = __shfl_up_sync(0xffffffffu, FC.hi, 1);            \
                __half2 s2 = __shfl_down_sync(0xffffffffu, FC.lo, 1);          \
                fLn = __high2half(s1); fRn = __low2half(s2);                   \
            }                                                                  \
            HC = comb_maxh(FC, fLn, fRn, lane);                                \
            H4 e3_ = min_h(vmin3h(FA, FB, FC), comb_minh(FB, fLo, fRo, lane)); \
            fLo = fLn; fRo = fRn;                                              \
            BC = hmax3h(e3_, lane);                                            \
            if (y >= yOUT) {                                 /* row y-4 */     \
                H4 D2 = vmax3h(BA, BB, BC);                                    \
                if (stok) {                                                    \
                    H4 d2 = relu_subh(FA, D2);               /* E2[y-4] */     \
                    H4 s = spf;                                                \
                    skel_updh(s, dprev);                                       \
                    skel_updh(s, d2);                                          \
                    *(H4*)(skb + (y - 4) * WW) = s;                            \
                    *(H4*)(dsb + (y - 4) * WW) = FA;                           \
                }                                                              \
            }                                                                  \
            if (y >= yD1) {                                  /* delta1 y-3 */  \
                H4 D1 = vmax3h(HA, HB, HC);                                    \
                dprev = relu_subh(EA, D1);                   /* E1[y-3] */     \
                if (stok) spf = *(const H4*)(skb + (y - 3) * WW);              \
            }                                                                  \
        } else {                                                               \
            {                                                                  \
                bool ldok = colok && ((unsigned)(y + 1) < (unsigned)HH);       \
                pf = ldok ? *(const H4*)srcp : h4_inf();                       \
                srcp += WW;                                                    \
            }                                                                  \
            IC = icur;                                                         \
            EC = min_h(vmin3h(IA, IB, IC), hmin3h(IB, lane));                  \
            FC = min_h(vmin3h(EA, EB, EC), hmin3h(EB, lane));                  \
            HC = hmax3h(selneg(FC, colok &&                                    \
                     (unsigned)(y - 2) < (unsigned)HH), lane);                 \
            H4 e3_ = min_h(vmin3h(FA, FB, FC), hmin3h(FB, lane));              \
            BC = hmax3h(selneg(e3_, colok &&                                   \
                     (unsigned)(y - 3) < (unsigned)HH), lane);                 \
            if (y >= yOUT) {                                                   \
                H4 D2 = vmax3h(BA, BB, BC);                                    \
                if (stok) {                                                    \
                    H4 d2 = relu_subh(FA, D2);                                 \
                    H4 s = spf;                                                \
                    skel_updh(s, dprev);                                       \
                    skel_updh(s, d2);                                          \
                    *(H4*)(skb + (y - 4) * WW) = s;                            \
                    *(H4*)(dsb + (y - 4) * WW) = FA;                           \
                }                                                              \
            }                                                                  \
            if (y >= yD1) {                                                    \
                H4 D1 = vmax3h(HA, HB, HC);                                    \
                dprev = relu_subh(EA, D1);                                     \
                if (stok && (unsigned)(y - 3) < (unsigned)HH)                  \
                    spf = *(const H4*)(skb + (y - 3) * WW);                    \
            }                                                                  \
        }                                                                      \
        ++y;                                                                   \
    }

    // 24 steps = 8 groups of 3 (ring rotation by argument permutation)
#pragma unroll 1
    for (int k = 0; k < 8; ++k) {
        STEP2(ia, ib, ic, ea, eb, ec, fa, fb, fc, ha, hb, hc, ba, bb, bc);
        STEP2(ib, ic, ia, eb, ec, ea, fb, fc, fa, hb, hc, ha, bb, bc, ba);
        STEP2(ic, ia, ib, ec, ea, eb, fc, fa, fb, hc, ha, hb, bc, ba, bb);
    }
#undef STEP2
}

__global__ void __launch_bounds__(IT2_BLOCK, 6) k_iter2(int flip) {
    const int lane = threadIdx.x & 31;
    const int gw = (blockIdx.x * IT2_BLOCK + threadIdx.x) >> 5;
    const int strip = gw % STRIPS;
    const int t = gw / STRIPS;
    const int chunk = t & (CHUNKS - 1);
    const int z = t / CHUNKS;

    const __half* __restrict__ src = (flip ? g_imgB : g_imgA) + z * HWSZ;
    __half* __restrict__ dst = (flip ? g_imgA : g_imgB) + z * HWSZ;
    __half* __restrict__ skel = g_skel + z * HWSZ;

    const int c0 = strip * 120 - 4 + 4 * lane;
    const int r0 = chunk * CHUNK_ROWS;

    // interior: all touched rows/cols in range for all lanes
    const bool interior = (chunk >= 1) && (chunk <= 30) &&
                          (strip >= 1) && (strip <= 3);
    if (interior)
        it2_body<true>(src, dst, skel, lane, c0, r0);
    else
        it2_body<false>(src, dst, skel, lane, c0, r0);
}

// ---------------------------------------------------------------------------
// Reductions
// ---------------------------------------------------------------------------
__global__ void k_zero() {
    int t = threadIdx.x;
    if (t < NIMG * 7) ((double*)g_sums)[t] = 0.0;
}

__global__ void k_reduce(const float* __restrict__ tgt) {
    const int n = blockIdx.y;
    const H4* __restrict__ sp = (const H4*)(g_skel + n * HWSZ);
    const H4* __restrict__ sl = (const H4*)(g_skel + (NIMG + n) * HWSZ);
    const float4* __restrict__ pp = (const float4*)(g_p + n * HWSZ);
    const float4* __restrict__ tt = (const float4*)(tgt + n * HWSZ);
    const int n4 = HWSZ / 4;

    double a0 = 0, a1 = 0, a2 = 0, a3 = 0, a4 = 0, a5 = 0, a6 = 0;
    for (int i = blockIdx.x * blockDim.x + threadIdx.x; i < n4;
         i += gridDim.x * blockDim.x) {
        H4 s1h = sp[i], s2h = sl[i];
        float2 s1lo = __half22float2(s1h.lo), s1hi = __half22float2(s1h.hi);
        float2 s2lo = __half22float2(s2h.lo), s2hi = __half22float2(s2h.hi);
        float4 pv = pp[i], tv = tt[i];
        a0 += (double)(s1lo.x * tv.x + s1lo.y * tv.y + s1hi.x * tv.z + s1hi.y * tv.w);
        a1 += (double)(s1lo.x + s1lo.y + s1hi.x + s1hi.y);
        a2 += (double)(s2lo.x * pv.x + s2lo.y * pv.y + s2hi.x * pv.z + s2hi.y * pv.w);
        a3 += (double)(s2lo.x + s2lo.y + s2hi.x + s2hi.y);
        a4 += (double)(pv.x * tv.x + pv.y * tv.y + pv.z * tv.z + pv.w * tv.w);
        a5 += (double)(pv.x + pv.y + pv.z + pv.w);
        a6 += (double)(tv.x + tv.y + tv.z + tv.w);
    }
#pragma unroll
    for (int o = 16; o > 0; o >>= 1) {
        a0 += __shfl_down_sync(0xffffffffu, a0, o);
        a1 += __shfl_down_sync(0xffffffffu, a1, o);
        a2 += __shfl_down_sync(0xffffffffu, a2, o);
        a3 += __shfl_down_sync(0xffffffffu, a3, o);
        a4 += __shfl_down_sync(0xffffffffu, a4, o);
        a5 += __shfl_down_sync(0xffffffffu, a5, o);
        a6 += __shfl_down_sync(0xffffffffu, a6, o);
    }
    if ((threadIdx.x & 31) == 0) {
        atomicAdd(&g_sums[n][0], a0);
        atomicAdd(&g_sums[n][1], a1);
        atomicAdd(&g_sums[n][2], a2);
        atomicAdd(&g_sums[n][3], a3);
        atomicAdd(&g_sums[n][4], a4);
        atomicAdd(&g_sums[n][5], a5);
        atomicAdd(&g_sums[n][6], a6);
    }
}

__global__ void k_final(float* __restrict__ out, int out_size) {
    if (threadIdx.x == 0 && blockIdx.x == 0) {
        const double smooth = 1.0;
        double cl = 0.0, dice = 0.0;
        for (int n = 0; n < NIMG; n++) {
            double A = g_sums[n][0], B = g_sums[n][1], C = g_sums[n][2],
                   D = g_sums[n][3], E = g_sums[n][4], F = g_sums[n][5],
                   G = g_sums[n][6];
            double tprec = (A + smooth) / (B + smooth);
            double tsens = (C + smooth) / (D + smooth);
            cl += 1.0 - 2.0 * tprec * tsens / (tprec + tsens);
            dice += 1.0 - 2.0 * (E + smooth) / (F + G + smooth);
        }
        cl /= NIMG;
        dice /= NIMG;
        float loss = (float)(0.7 * dice + 0.3 * cl);
        for (int i = 0; i < out_size; i++) out[i] = loss;
    }
}

// ---------------------------------------------------------------------------
extern "C" void kernel_launch(void* const* d_in, const int* in_sizes, int n_in,
                              void* d_out, int out_size) {
    const float* output = (const float*)d_in[0];
    const float* target = (const float*)d_in[1];
    float* out = (float*)d_out;

    k_init<<<1024, 256>>>((const float4*)output, (const float4*)target);

    k_open_init<<<SWEEP_GRID, SWEEP_BLOCK>>>();

    // 50 iterations = 25 fused-2 launches
    for (int j = 0; j < NITER / 2; ++j) {
        k_iter2<<<IT2_GRID, IT2_BLOCK>>>(j & 1);
    }

    k_zero<<<1, 64>>>();
    k_reduce<<<dim3(32, NIMG), 256>>>(target);
    k_final<<<1, 32>>>(out, out_size);
}

// round 15
// speedup vs baseline: 1.1293x; 1.0639x over previous
#include <cuda_runtime.h>
#include <cuda_fp16.h>
#include <math.h>

#define WW 512
#define HH 512
#define NIMG 8
#define HWSZ (HH * WW)
#define NPLANES 16            // 2 streams (p, target) x 8 samples
#define TOTALSZ (NPLANES * HWSZ)
#define NITER 50

#define STRIPS 5              // 5 strips x 120 output cols (lanes 1..30 of 4-col lanes)
#define CHUNK_ROWS 16
#define CHUNKS 32             // 512 / 16
#define WARPS_TOTAL (STRIPS * CHUNKS * NPLANES)   // 2560

#define SWEEP_BLOCK 256
#define SWEEP_GRID (WARPS_TOTAL / (SWEEP_BLOCK / 32))  // 320

#define IT2_BLOCK 128
#define IT2_GRID (WARPS_TOTAL / (IT2_BLOCK / 32))      // 640

// Static scratch (no allocations allowed in kernel_launch)
__device__ float  g_p[NIMG * HWSZ];    // sigmoid(output) fp32, for the Dice-side reduction
__device__ __half g_imgA[TOTALSZ];     // ping (fp16)
__device__ __half g_imgB[TOTALSZ];     // pong (fp16)
__device__ __half g_skel[TOTALSZ];     // skeleton accumulators (fp16)
__device__ double g_sums[NIMG][7];     // per-sample reduction accumulators

// ---------------------------------------------------------------------------
// fp16x4 helpers: one lane owns 4 adjacent columns as {lo=(c0,c1), hi=(c2,c3)}
// ---------------------------------------------------------------------------
struct __align__(8) H4 { __half2 lo, hi; };

__device__ __forceinline__ __half h_inf()  { return __ushort_as_half((unsigned short)0x7C00); }
__device__ __forceinline__ __half h_ninf() { return __ushort_as_half((unsigned short)0xFC00); }
__device__ __forceinline__ H4 h4fill(__half v) { __half2 p = __half2half2(v); H4 r; r.lo = p; r.hi = p; return r; }
__device__ __forceinline__ H4 h4_inf()  { return h4fill(h_inf()); }
__device__ __forceinline__ H4 h4_ninf() { return h4fill(h_ninf()); }
__device__ __forceinline__ H4 h4_zero() { return h4fill(__ushort_as_half(0)); }

__device__ __forceinline__ H4 min_h(H4 a, H4 b) { H4 r; r.lo = __hmin2(a.lo, b.lo); r.hi = __hmin2(a.hi, b.hi); return r; }
__device__ __forceinline__ H4 max_h(H4 a, H4 b) { H4 r; r.lo = __hmax2(a.lo, b.lo); r.hi = __hmax2(a.hi, b.hi); return r; }
__device__ __forceinline__ H4 vmin3h(H4 a, H4 b, H4 c) { return min_h(min_h(a, b), c); }
__device__ __forceinline__ H4 vmax3h(H4 a, H4 b, H4 c) { return max_h(max_h(a, b), c); }

// horizontal combine with EXPLICIT edge values (no shuffle inside)
__device__ __forceinline__ H4 comb_minh(H4 v, __half L, __half R, int lane) {
    if (lane == 0)  L = h_inf();
    if (lane == 31) R = h_inf();
    __half2 La = __halves2half2(L, __low2half(v.lo));
    __half2 bc = __halves2half2(__high2half(v.lo), __low2half(v.hi));
    __half2 dR = __halves2half2(__high2half(v.hi), R);
    H4 o;
    o.lo = __hmin2(__hmin2(La, v.lo), bc);
    o.hi = __hmin2(__hmin2(bc, v.hi), dR);
    return o;
}
__device__ __forceinline__ H4 comb_maxh(H4 v, __half L, __half R, int lane) {
    if (lane == 0)  L = h_ninf();
    if (lane == 31) R = h_ninf();
    __half2 La = __halves2half2(L, __low2half(v.lo));
    __half2 bc = __halves2half2(__high2half(v.lo), __low2half(v.hi));
    __half2 dR = __halves2half2(__high2half(v.hi), R);
    H4 o;
    o.lo = __hmax2(__hmax2(La, v.lo), bc);
    o.hi = __hmax2(__hmax2(bc, v.hi), dR);
    return o;
}
// classic same-step variants
__device__ __forceinline__ H4 hmin3h(H4 v, int lane) {
    __half2 fl = __shfl_up_sync(0xffffffffu, v.hi, 1);
    __half2 fr = __shfl_down_sync(0xffffffffu, v.lo, 1);
    return comb_minh(v, __high2half(fl), __low2half(fr), lane);
}
__device__ __forceinline__ H4 hmax3h(H4 v, int lane) {
    __half2 fl = __shfl_up_sync(0xffffffffu, v.hi, 1);
    __half2 fr = __shfl_down_sync(0xffffffffu, v.lo, 1);
    return comb_maxh(v, __high2half(fl), __low2half(fr), lane);
}
__device__ __forceinline__ H4 relu_subh(H4 a, H4 b) {
    __half2 z = __half2half2(__ushort_as_half(0));
    H4 r;
    r.lo = __hmax2(__hsub2(a.lo, b.lo), z);
    r.hi = __hmax2(__hsub2(a.hi, b.hi), z);
    return r;
}
__device__ __forceinline__ H4 selneg(H4 v, bool ok) { return ok ? v : h4_ninf(); }
// s += relu(d - s*d)
__device__ __forceinline__ void skel_updh(H4& s, H4 d) {
    s.lo = __hadd2(s.lo, __hfma2_relu(__hneg2(s.lo), d.lo, d.lo));
    s.hi = __hadd2(s.hi, __hfma2_relu(__hneg2(s.hi), d.hi, d.hi));
}

// ---------------------------------------------------------------------------
// Init: p = sigmoid(output); g_p fp32; imgA[stream0]=half(p), imgA[stream1]=half(target)
// ---------------------------------------------------------------------------
__global__ void k_init(const float4* __restrict__ out, const float4* __restrict__ tgt) {
    int i = blockIdx.x * blockDim.x + threadIdx.x;
    int stride = gridDim.x * blockDim.x;
    float4* gp = (float4*)g_p;
    H4* ga = (H4*)g_imgA;
    H4* gb = (H4*)(g_imgA + NIMG * HWSZ);
    const int n4 = NIMG * HWSZ / 4;
    for (; i < n4; i += stride) {
        float4 o = out[i];
        float4 v;
        v.x = 1.0f / (1.0f + expf(-o.x));
        v.y = 1.0f / (1.0f + expf(-o.y));
        v.z = 1.0f / (1.0f + expf(-o.z));
        v.w = 1.0f / (1.0f + expf(-o.w));
        gp[i] = v;
        H4 hv; hv.lo = __floats2half2_rn(v.x, v.y); hv.hi = __floats2half2_rn(v.z, v.w);
        ga[i] = hv;
        float4 t = tgt[i];
        H4 ht; ht.lo = __floats2half2_rn(t.x, t.y); ht.hi = __floats2half2_rn(t.z, t.w);
        gb[i] = ht;
    }
}

// ---------------------------------------------------------------------------
// Warp-sweep open-init:  skel = relu(img - dilate(erode(img)))   (fp16)
// ---------------------------------------------------------------------------
__global__ void __launch_bounds__(SWEEP_BLOCK, 3) k_open_init() {
    const int lane = threadIdx.x & 31;
    const int gw = (blockIdx.x * SWEEP_BLOCK + threadIdx.x) >> 5;
    const int strip = gw % STRIPS;
    const int t = gw / STRIPS;
    const int chunk = t & (CHUNKS - 1);
    const int z = t / CHUNKS;

    const __half* __restrict__ src = g_imgA + z * HWSZ;
    __half* __restrict__ skel = g_skel + z * HWSZ;

    const int c0 = strip * 120 - 4 + 4 * lane;
    const bool colok = (c0 >= 0) && (c0 < WW);
    const bool stok = (lane >= 1) && (lane <= 30) && (c0 < WW);
    const int r0 = chunk * CHUNK_ROWS;
    const int ylim = r0 + 2;

    int y = r0 - 2;
    const __half* srcp = src + y * WW + c0;
    __half* const skb = skel + c0;

    H4 ia = h4_inf(), ib = h4_inf(), ic;
    H4 ha = h4_ninf(), hb = h4_ninf(), hc;

#define OPEN_STEP(IA, IB, IC, HA, HB, HC)                                      \
    {                                                                          \
        bool ldok = colok && ((unsigned)y < (unsigned)HH);                     \
        IC = ldok ? *(const H4*)srcp : h4_inf();                               \
        H4 e1_ = min_h(vmin3h(IA, IB, IC), hmin3h(IB, lane));                  \
        if (!colok || (unsigned)(y - 1) >= (unsigned)HH) e1_ = h4_ninf();      \
        HC = hmax3h(e1_, lane);                                                \
        if (y >= ylim) {                                                       \
            H4 d_ = vmax3h(HA, HB, HC);                                        \
            if (stok) {                                                        \
                H4 o_ = relu_subh(IA, d_);                                     \
                *(H4*)(skb + (y - 2) * WW) = o_;                               \
            }                                                                  \
        }                                                                      \
        ++y;                                                                   \
        srcp += WW;                                                            \
    }

#pragma unroll 1
    for (int k = 0; k < 6; ++k) {
        OPEN_STEP(ia, ib, ic, ha, hb, hc);
        OPEN_STEP(ib, ic, ia, hb, hc, ha);
        OPEN_STEP(ic, ia, ib, hc, ha, hb);
    }
    OPEN_STEP(ia, ib, ic, ha, hb, hc);
    OPEN_STEP(ib, ic, ia, hb, hc, ha);
#undef OPEN_STEP
}

// ---------------------------------------------------------------------------
// Fused TWO skeleton iterations, fp16 lanes, 4-way specialization:
//   RIN: all rows in range (chunks 1..30)   CIN: all cols in range (strips 1..3)
// Erode-side OOB contamination is dominated under min (no masks needed);
// only the two hmax feeds (H from E2, B from E3) need selneg masks, plus
// guarded loads/stores. I/E edges always pre-shuffled one step ahead; F edges
// pre-shuffled for E3 (unmasked erode feed). Interior reuses the F edges for
// the H hmax too; masked variants shuffle the masked F row same-step.
// ---------------------------------------------------------------------------
template<bool RIN, bool CIN>
__device__ __forceinline__ void it2_body(
    const __half* __restrict__ src, __half* __restrict__ dst,
    __half* __restrict__ skel, const int lane, const int c0, const int r0)
{
    const bool colok = CIN || ((c0 >= 0) && (c0 < WW));
    const bool stok = (lane >= 1) && (lane <= 30) && (CIN || (c0 < WW));
    const int yD1 = r0 + 3;
    const int yOUT = r0 + 4;

    int y = r0 - 4;
    H4 pf;
    {
        bool ldok = colok && (RIN || (unsigned)y < (unsigned)HH);
        pf = ldok ? *(const H4*)(src + y * WW + c0) : h4_inf();
    }
    const __half* srcp = src + (y + 1) * WW + c0;
    __half* const skb = skel + c0;
    __half* const dsb = dst + c0;

    H4 ia = h4_inf(), ib = h4_inf(), ic;        // I ring
    H4 ea = h4_inf(), eb = h4_inf(), ec;        // E1 ring
    H4 fa = h4_inf(), fb = h4_inf(), fc;        // E2 ring
    H4 ha = h4_ninf(), hb = h4_ninf(), hc;      // H = hmax(E2)
    H4 ba = h4_ninf(), bb = h4_ninf(), bc;      // Hb = hmax(E3)
    H4 dprev = h4_zero();                       // delta1[y-4]
    H4 spf = h4_zero();                         // skel prefetch
    // saved edges: of I row y-1, E1 row y-2, F row y-3 (unmasked, erode feeds)
    __half iL = h_inf(), iR = h_inf();
    __half eL = h_inf(), eR = h_inf();
    __half fLo = h_inf(), fRo = h_inf();

#define STEP2(IA, IB, IC, EA, EB, EC, FA, FB, FC, HA, HB, HC, BA, BB, BC)      \
    {                                                                          \
        H4 icur = pf;                                                          \
        {                                                                      \
            bool ldok = colok && (RIN || (unsigned)(y + 1) < (unsigned)HH);    \
            pf = ldok ? *(const H4*)srcp : h4_inf();                           \
            srcp += WW;                                                        \
        }                                                                      \
        IC = icur;                                                             \
        /* E1[y-1]: edges of I[y-1] saved last step */                         \
        EC = min_h(vmin3h(IA, IB, IC), comb_minh(IB, iL, iR, lane));           \
        {                                                                      \
            __half2 s1 = __shfl_up_sync(0xffffffffu, icur.hi, 1);              \
            __half2 s2 = __shfl_down_sync(0xffffffffu, icur.lo, 1);            \
            iL = __high2half(s1); iR = __low2half(s2);                         \
        }                                                                      \
        /* E2[y-2]: edges of E1[y-2] saved last step */                        \
        FC = min_h(vmin3h(EA, EB, EC), comb_minh(EB, eL, eR, lane));           \
        {                                                                      \
            __half2 s1 = __shfl_up_sync(0xffffffffu, EC.hi, 1);                \
            __half2 s2 = __shfl_down_sync(0xffffffffu, EC.lo, 1);              \
            eL = __high2half(s1); eR = __low2half(s2);                         \
        }                                                                      \
        /* F[y-2] edges (unmasked): E3's erode next step; interior H too */    \
        __half fLn, fRn;                                                       \
        {                                                                      \
            __half2 s1 = __shfl_up_sync(0xffffffffu, FC.hi, 1);                \
            __half2 s2 = __shfl_down_sync(0xffffffffu, FC.lo, 1);              \
            fLn = __high2half(s1); fRn = __low2half(s2);                       \
        }                                                                      \
        /* H[y-2..] : hmax of masked F */                                      \
        if (RIN && CIN) {                                                      \
            HC = comb_maxh(FC, fLn, fRn, lane);                                \
        } else {                                                               \
            bool okH = colok && (RIN || (unsigned)(y - 2) < (unsigned)HH);     \
            HC = hmax3h(selneg(FC, okH), lane);                                \
        }                                                                      \
        /* E3[y-3] = erode(F), unmasked edges saved last step */               \
        H4 e3_ = min_h(vmin3h(FA, FB, FC), comb_minh(FB, fLo, fRo, lane));     \
        fLo = fLn; fRo = fRn;                                                  \
        /* B[y-3] = hmax of masked E3 (same-step shuffle) */                   \
        if (RIN && CIN) {                                                      \
            BC = hmax3h(e3_, lane);                                            \
        } else {                                                               \
            bool okB = colok && (RIN || (unsigned)(y - 3) < (unsigned)HH);     \
            BC = hmax3h(selneg(e3_, okB), lane);                               \
        }                                                                      \
        if (y >= yOUT) {                                     /* row y-4 */     \
            H4 D2 = vmax3h(BA, BB, BC);                                        \
            if (stok) {                                                        \
                H4 d2 = relu_subh(FA, D2);                   /* E2[y-4] */     \
                H4 s = spf;                                                    \
                skel_updh(s, dprev);                                           \
                skel_updh(s, d2);                                              \
                *(H4*)(skb + (y - 4) * WW) = s;                                \
                *(H4*)(dsb + (y - 4) * WW) = FA;                               \
            }                                                                  \
        }                                                                      \
        if (y >= yD1) {                                      /* delta1 y-3 */  \
            H4 D1 = vmax3h(HA, HB, HC);                                        \
            dprev = relu_subh(EA, D1);                       /* E1[y-3] */     \
            if (stok && (RIN || (unsigned)(y - 3) < (unsigned)HH))             \
                spf = *(const H4*)(skb + (y - 3) * WW);                        \
        }                                                                      \
        ++y;                                                                   \
    }

    // 24 steps = 8 groups of 3 (ring rotation by argument permutation)
#pragma unroll 1
    for (int k = 0; k < 8; ++k) {
        STEP2(ia, ib, ic, ea, eb, ec, fa, fb, fc, ha, hb, hc, ba, bb, bc);
        STEP2(ib, ic, ia, eb, ec, ea, fb, fc, fa, hb, hc, ha, bb, bc, ba);
        STEP2(ic, ia, ib, ec, ea, eb, fc, fa, fb, hc, ha, hb, bc, ba, bb);
    }
#undef STEP2
}

__global__ void __launch_bounds__(IT2_BLOCK, 6) k_iter2(int flip) {
    const int lane = threadIdx.x & 31;
    const int gw = (blockIdx.x * IT2_BLOCK + threadIdx.x) >> 5;
    const int strip = gw % STRIPS;
    const int t = gw / STRIPS;
    const int chunk = t & (CHUNKS - 1);
    const int z = t / CHUNKS;

    const __half* __restrict__ src = (flip ? g_imgB : g_imgA) + z * HWSZ;
    __half* __restrict__ dst = (flip ? g_imgA : g_imgB) + z * HWSZ;
    __half* __restrict__ skel = g_skel + z * HWSZ;

    const int c0 = strip * 120 - 4 + 4 * lane;
    const int r0 = chunk * CHUNK_ROWS;

    const bool rin = (chunk >= 1) && (chunk <= 30);
    const bool cin = (strip >= 1) && (strip <= 3);
    if (rin) {
        if (cin) it2_body<true, true>(src, dst, skel, lane, c0, r0);
        else     it2_body<true, false>(src, dst, skel, lane, c0, r0);
    } else {
        if (cin) it2_body<false, true>(src, dst, skel, lane, c0, r0);
        else     it2_body<false, false>(src, dst, skel, lane, c0, r0);
    }
}

// ---------------------------------------------------------------------------
// Reductions
// ---------------------------------------------------------------------------
__global__ void k_zero() {
    int t = threadIdx.x;
    if (t < NIMG * 7) ((double*)g_sums)[t] = 0.0;
}

__global__ void k_reduce(const float* __restrict__ tgt) {
    const int n = blockIdx.y;
    const H4* __restrict__ sp = (const H4*)(g_skel + n * HWSZ);
    const H4* __restrict__ sl = (const H4*)(g_skel + (NIMG + n) * HWSZ);
    const float4* __restrict__ pp = (const float4*)(g_p + n * HWSZ);
    const float4* __restrict__ tt = (const float4*)(tgt + n * HWSZ);
    const int n4 = HWSZ / 4;

    double a0 = 0, a1 = 0, a2 = 0, a3 = 0, a4 = 0, a5 = 0, a6 = 0;
    for (int i = blockIdx.x * blockDim.x + threadIdx.x; i < n4;
         i += gridDim.x * blockDim.x) {
        H4 s1h = sp[i], s2h = sl[i];
        float2 s1lo = __half22float2(s1h.lo), s1hi = __half22float2(s1h.hi);
        float2 s2lo = __half22float2(s2h.lo), s2hi = __half22float2(s2h.hi);
        float4 pv = pp[i], tv = tt[i];
        a0 += (double)(s1lo.x * tv.x + s1lo.y * tv.y + s1hi.x * tv.z + s1hi.y * tv.w);
        a1 += (double)(s1lo.x + s1lo.y + s1hi.x + s1hi.y);
        a2 += (double)(s2lo.x * pv.x + s2lo.y * pv.y + s2hi.x * pv.z + s2hi.y * pv.w);
        a3 += (double)(s2lo.x + s2lo.y + s2hi.x + s2hi.y);
        a4 += (double)(pv.x * tv.x + pv.y * tv.y + pv.z * tv.z + pv.w * tv.w);
        a5 += (double)(pv.x + pv.y + pv.z + pv.w);
        a6 += (double)(tv.x + tv.y + tv.z + tv.w);
    }
#pragma unroll
    for (int o = 16; o > 0; o >>= 1) {
        a0 += __shfl_down_sync(0xffffffffu, a0, o);
        a1 += __shfl_down_sync(0xffffffffu, a1, o);
        a2 += __shfl_down_sync(0xffffffffu, a2, o);
        a3 += __shfl_down_sync(0xffffffffu, a3, o);
        a4 += __shfl_down_sync(0xffffffffu, a4, o);
        a5 += __shfl_down_sync(0xffffffffu, a5, o);
        a6 += __shfl_down_sync(0xffffffffu, a6, o);
    }
    if ((threadIdx.x & 31) == 0) {
        atomicAdd(&g_sums[n][0], a0);
        atomicAdd(&g_sums[n][1], a1);
        atomicAdd(&g_sums[n][2], a2);
        atomicAdd(&g_sums[n][3], a3);
        atomicAdd(&g_sums[n][4], a4);
        atomicAdd(&g_sums[n][5], a5);
        atomicAdd(&g_sums[n][6], a6);
    }
}

__global__ void k_final(float* __restrict__ out, int out_size) {
    if (threadIdx.x == 0 && blockIdx.x == 0) {
        const double smooth = 1.0;
        double cl = 0.0, dice = 0.0;
        for (int n = 0; n < NIMG; n++) {
            double A = g_sums[n][0], B = g_sums[n][1], C = g_sums[n][2],
                   D = g_sums[n][3], E = g_sums[n][4], F = g_sums[n][5],
                   G = g_sums[n][6];
            double tprec = (A + smooth) / (B + smooth);
            double tsens = (C + smooth) / (D + smooth);
            cl += 1.0 - 2.0 * tprec * tsens / (tprec + tsens);
            dice += 1.0 - 2.0 * (E + smooth) / (F + G + smooth);
        }
        cl /= NIMG;
        dice /= NIMG;
        float loss = (float)(0.7 * dice + 0.3 * cl);
        for (int i = 0; i < out_size; i++) out[i] = loss;
    }
}

// ---------------------------------------------------------------------------
extern "C" void kernel_launch(void* const* d_in, const int* in_sizes, int n_in,
                              void* d_out, int out_size) {
    const float* output = (const float*)d_in[0];
    const float* target = (const float*)d_in[1];
    float* out = (float*)d_out;

    k_init<<<1024, 256>>>((const float4*)output, (const float4*)target);

    k_open_init<<<SWEEP_GRID, SWEEP_BLOCK>>>();

    // 50 iterations = 25 fused-2 launches
    for (int j = 0; j < NITER / 2; ++j) {
        k_iter2<<<IT2_GRID, IT2_BLOCK>>>(j & 1);
    }

    k_zero<<<1, 64>>>();
    k_reduce<<<dim3(32, NIMG), 256>>>(target);
    k_final<<<1, 32>>>(out, out_size);
}

// round 16
// speedup vs baseline: 1.1524x; 1.0205x over previous
#include <cuda_runtime.h>
#include <cuda_fp16.h>
#include <math.h>

#define WW 512
#define HH 512
#define NIMG 8
#define HWSZ (HH * WW)
#define NPLANES 16            // 2 streams (p, target) x 8 samples
#define TOTALSZ (NPLANES * HWSZ)
#define NITER 50

#define STRIPS 5              // 5 strips x 120 output cols (lanes 1..30 of 4-col lanes)
#define CHUNK_ROWS 16
#define CHUNKS 32             // 512 / 16
#define WARPS_TOTAL (STRIPS * CHUNKS * NPLANES)   // 2560

#define IT2_BLOCK 128
#define IT2_GRID (WARPS_TOTAL / (IT2_BLOCK / 32))      // 640

// Static scratch (no allocations allowed in kernel_launch)
__device__ __half g_imgA[TOTALSZ];     // ping (fp16)
__device__ __half g_imgB[TOTALSZ];     // pong (fp16)
__device__ __half g_skel[TOTALSZ];     // skeleton accumulators (fp16)
__device__ double g_sums[NIMG][7];     // per-sample reduction accumulators

// ---------------------------------------------------------------------------
// fp16x4 helpers: one lane owns 4 adjacent columns as {lo=(c0,c1), hi=(c2,c3)}
// ---------------------------------------------------------------------------
struct __align__(8) H4 { __half2 lo, hi; };

__device__ __forceinline__ __half h_inf()  { return __ushort_as_half((unsigned short)0x7C00); }
__device__ __forceinline__ __half h_ninf() { return __ushort_as_half((unsigned short)0xFC00); }
__device__ __forceinline__ H4 h4fill(__half v) { __half2 p = __half2half2(v); H4 r; r.lo = p; r.hi = p; return r; }
__device__ __forceinline__ H4 h4_inf()  { return h4fill(h_inf()); }
__device__ __forceinline__ H4 h4_ninf() { return h4fill(h_ninf()); }
__device__ __forceinline__ H4 h4_zero() { return h4fill(__ushort_as_half(0)); }

__device__ __forceinline__ H4 min_h(H4 a, H4 b) { H4 r; r.lo = __hmin2(a.lo, b.lo); r.hi = __hmin2(a.hi, b.hi); return r; }
__device__ __forceinline__ H4 max_h(H4 a, H4 b) { H4 r; r.lo = __hmax2(a.lo, b.lo); r.hi = __hmax2(a.hi, b.hi); return r; }
__device__ __forceinline__ H4 vmin3h(H4 a, H4 b, H4 c) { return min_h(min_h(a, b), c); }
__device__ __forceinline__ H4 vmax3h(H4 a, H4 b, H4 c) { return max_h(max_h(a, b), c); }

// horizontal combine with EXPLICIT edge values (no shuffle inside)
__device__ __forceinline__ H4 comb_minh(H4 v, __half L, __half R, int lane) {
    if (lane == 0)  L = h_inf();
    if (lane == 31) R = h_inf();
    __half2 La = __halves2half2(L, __low2half(v.lo));
    __half2 bc = __halves2half2(__high2half(v.lo), __low2half(v.hi));
    __half2 dR = __halves2half2(__high2half(v.hi), R);
    H4 o;
    o.lo = __hmin2(__hmin2(La, v.lo), bc);
    o.hi = __hmin2(__hmin2(bc, v.hi), dR);
    return o;
}
__device__ __forceinline__ H4 comb_maxh(H4 v, __half L, __half R, int lane) {
    if (lane == 0)  L = h_ninf();
    if (lane == 31) R = h_ninf();
    __half2 La = __halves2half2(L, __low2half(v.lo));
    __half2 bc = __halves2half2(__high2half(v.lo), __low2half(v.hi));
    __half2 dR = __halves2half2(__high2half(v.hi), R);
    H4 o;
    o.lo = __hmax2(__hmax2(La, v.lo), bc);
    o.hi = __hmax2(__hmax2(bc, v.hi), dR);
    return o;
}
// classic same-step variants
__device__ __forceinline__ H4 hmin3h(H4 v, int lane) {
    __half2 fl = __shfl_up_sync(0xffffffffu, v.hi, 1);
    __half2 fr = __shfl_down_sync(0xffffffffu, v.lo, 1);
    return comb_minh(v, __high2half(fl), __low2half(fr), lane);
}
__device__ __forceinline__ H4 hmax3h(H4 v, int lane) {
    __half2 fl = __shfl_up_sync(0xffffffffu, v.hi, 1);
    __half2 fr = __shfl_down_sync(0xffffffffu, v.lo, 1);
    return comb_maxh(v, __high2half(fl), __low2half(fr), lane);
}
__device__ __forceinline__ H4 relu_subh(H4 a, H4 b) {
    __half2 z = __half2half2(__ushort_as_half(0));
    H4 r;
    r.lo = __hmax2(__hsub2(a.lo, b.lo), z);
    r.hi = __hmax2(__hsub2(a.hi, b.hi), z);
    return r;
}
__device__ __forceinline__ H4 selneg(H4 v, bool ok) { return ok ? v : h4_ninf(); }
// s += relu(d - s*d)
__device__ __forceinline__ void skel_updh(H4& s, H4 d) {
    s.lo = __hadd2(s.lo, __hfma2_relu(__hneg2(s.lo), d.lo, d.lo));
    s.hi = __hadd2(s.hi, __hfma2_relu(__hneg2(s.hi), d.hi, d.hi));
}

// ---------------------------------------------------------------------------
// Init: imgA[stream0]=half(sigmoid(output)), imgA[stream1]=half(target)
// ---------------------------------------------------------------------------
__global__ void k_init(const float4* __restrict__ out, const float4* __restrict__ tgt) {
    int i = blockIdx.x * blockDim.x + threadIdx.x;
    int stride = gridDim.x * blockDim.x;
    H4* ga = (H4*)g_imgA;
    H4* gb = (H4*)(g_imgA + NIMG * HWSZ);
    const int n4 = NIMG * HWSZ / 4;
    for (; i < n4; i += stride) {
        float4 o = out[i];
        float4 v;
        v.x = 1.0f / (1.0f + expf(-o.x));
        v.y = 1.0f / (1.0f + expf(-o.y));
        v.z = 1.0f / (1.0f + expf(-o.z));
        v.w = 1.0f / (1.0f + expf(-o.w));
        H4 hv; hv.lo = __floats2half2_rn(v.x, v.y); hv.hi = __floats2half2_rn(v.z, v.w);
        ga[i] = hv;
        float4 t = tgt[i];
        H4 ht; ht.lo = __floats2half2_rn(t.x, t.y); ht.hi = __floats2half2_rn(t.z, t.w);
        gb[i] = ht;
    }
}

// ---------------------------------------------------------------------------
// Shared pipeline-step core. FIRST=true additionally computes the open-init
// skel0 = relu(I - dilate(E1)) via an H0 ring + 2-step delay chain, replacing
// the skel load; FIRST=false loads/updates existing skel.
// Stages at step y:  E1[y-1], E2[y-2](=F), H=hmax(E2)[y-2], E3[y-3],
//                    B=hmax(E3)[y-3], (FIRST: H0=hmax(E1)[y-1])
// Outputs: delta1[y-3] (kept one step), row y-4: skel + both deltas, img=E2.
// ---------------------------------------------------------------------------
template<bool RIN, bool CIN, bool FIRST>
__device__ __forceinline__ void it2_core(
    const __half* __restrict__ src, __half* __restrict__ dst,
    __half* __restrict__ skel, const int lane, const int c0, const int r0)
{
    const bool colok = CIN || ((c0 >= 0) && (c0 < WW));
    const bool stok = (lane >= 1) && (lane <= 30) && (CIN || (c0 < WW));
    const int yD1 = r0 + 3;
    const int yOUT = r0 + 4;

    int y = r0 - 4;
    H4 pf;
    {
        bool ldok = colok && (RIN || (unsigned)y < (unsigned)HH);
        pf = ldok ? *(const H4*)(src + y * WW + c0) : h4_inf();
    }
    const __half* srcp = src + (y + 1) * WW + c0;
    __half* const skb = skel + c0;
    __half* const dsb = dst + c0;

    H4 ia = h4_inf(), ib = h4_inf(), ic;        // I ring
    H4 ea = h4_inf(), eb = h4_inf(), ec;        // E1 ring
    H4 fa = h4_inf(), fb = h4_inf(), fc;        // E2 ring
    H4 ha = h4_ninf(), hb = h4_ninf(), hc;      // H = hmax(E2)
    H4 ba = h4_ninf(), bb = h4_ninf(), bc;      // Hb = hmax(E3)
    H4 h0a = h4_ninf(), h0b = h4_ninf(), h0c;   // H0 = hmax(E1)    (FIRST)
    H4 skd1 = h4_zero(), skd2 = h4_zero();      // skel0 delay      (FIRST)
    H4 dprev = h4_zero();                       // delta1[y-4]
    H4 spf = h4_zero();                         // skel prefetch    (!FIRST)
    // saved edges: of I row y-1, E1 row y-2, F row y-3 (unmasked, erode feeds)
    __half iL = h_inf(), iR = h_inf();
    __half eL = h_inf(), eR = h_inf();
    __half fLo = h_inf(), fRo = h_inf();

#define STEP2(IA, IB, IC, EA, EB, EC, FA, FB, FC, HA, HB, HC, BA, BB, BC,      \
              H0A, H0B, H0C)                                                   \
    {                                                                          \
        H4 icur = pf;                                                          \
        {                                                                      \
            bool ldok = colok && (RIN || (unsigned)(y + 1) < (unsigned)HH);    \
            pf = ldok ? *(const H4*)srcp : h4_inf();                           \
            srcp += WW;                                                        \
        }                                                                      \
        IC = icur;                                                             \
        /* E1[y-1]: edges of I[y-1] saved last step */                         \
        EC = min_h(vmin3h(IA, IB, IC), comb_minh(IB, iL, iR, lane));           \
        {                                                                      \
            __half2 s1 = __shfl_up_sync(0xffffffffu, icur.hi, 1);              \
            __half2 s2 = __shfl_down_sync(0xffffffffu, icur.lo, 1);            \
            iL = __high2half(s1); iR = __low2half(s2);                         \
        }                                                                      \
        /* E2[y-2]: edges of E1[y-2] saved last step */                        \
        FC = min_h(vmin3h(EA, EB, EC), comb_minh(EB, eL, eR, lane));           \
        {                                                                      \
            __half2 s1 = __shfl_up_sync(0xffffffffu, EC.hi, 1);                \
            __half2 s2 = __shfl_down_sync(0xffffffffu, EC.lo, 1);              \
            eL = __high2half(s1); eR = __low2half(s2);                         \
        }                                                                      \
        /* FIRST: H0[y-1] = hmax(masked E1[y-1]) */                            \
        if (FIRST) {                                                           \
            if (RIN && CIN) {                                                  \
                H0C = comb_maxh(EC, eL, eR, lane);                             \
            } else {                                                           \
                bool ok0 = colok && (RIN || (unsigned)(y - 1) < (unsigned)HH); \
                H0C = hmax3h(selneg(EC, ok0), lane);                           \
            }                                                                  \
        }                                                                      \
        /* F[y-2] edges (unmasked): E3's erode next step; interior H too */    \
        __half fLn, fRn;                                                       \
        {                                                                      \
            __half2 s1 = __shfl_up_sync(0xffffffffu, FC.hi, 1);                \
            __half2 s2 = __shfl_down_sync(0xffffffffu, FC.lo, 1);              \
            fLn = __high2half(s1); fRn = __low2half(s2);                       \
        }                                                                      \
        /* H[y-2] : hmax of masked F */                                        \
        if (RIN && CIN) {                                                      \
            HC = comb_maxh(FC, fLn, fRn, lane);                                \
        } else {                                                               \
            bool okH = colok && (RIN || (unsigned)(y - 2) < (unsigned)HH);     \
            HC = hmax3h(selneg(FC, okH), lane);                                \
        }                                                                      \
        /* E3[y-3] = erode(F), unmasked edges saved last step */               \
        H4 e3_ = min_h(vmin3h(FA, FB, FC), comb_minh(FB, fLo, fRo, lane));     \
        fLo = fLn; fRo = fRn;                                                  \
        /* B[y-3] = hmax of masked E3 (same-step shuffle) */                   \
        if (RIN && CIN) {                                                      \
            BC = hmax3h(e3_, lane);                                            \
        } else {                                                               \
            bool okB = colok && (RIN || (unsigned)(y - 3) < (unsigned)HH);     \
            BC = hmax3h(selneg(e3_, okB), lane);                               \
        }                                                                      \
        if (y >= yOUT) {                                     /* row y-4 */     \
            H4 D2 = vmax3h(BA, BB, BC);                                        \
            if (stok) {                                                        \
                H4 d2 = relu_subh(FA, D2);                   /* E2[y-4] */     \
                H4 s = FIRST ? skd2 : spf;                                     \
                skel_updh(s, dprev);                                           \
                skel_updh(s, d2);                                              \
                *(H4*)(skb + (y - 4) * WW) = s;                                \
                *(H4*)(dsb + (y - 4) * WW) = FA;                               \
            }                                                                  \
        }                                                                      \
        if (y >= yD1) {                                      /* delta1 y-3 */  \
            H4 D1 = vmax3h(HA, HB, HC);                                        \
            dprev = relu_subh(EA, D1);                       /* E1[y-3] */     \
            if (!FIRST && stok && (RIN || (unsigned)(y - 3) < (unsigned)HH))   \
                spf = *(const H4*)(skb + (y - 3) * WW);                        \
        }                                                                      \
        /* FIRST: skel0[y-2] = relu(I[y-2] - vmax(H0)), delayed 2 steps */     \
        if (FIRST) {                                                           \
            H4 D0 = vmax3h(H0A, H0B, H0C);                                     \
            skd2 = skd1;                                                       \
            skd1 = relu_subh(IA, D0);                                          \
        }                                                                      \
        ++y;                                                                   \
    }

    // 24 steps = 8 groups of 3 (ring rotation by argument permutation)
#pragma unroll 1
    for (int k = 0; k < 8; ++k) {
        STEP2(ia, ib, ic, ea, eb, ec, fa, fb, fc, ha, hb, hc, ba, bb, bc, h0a, h0b, h0c);
        STEP2(ib, ic, ia, eb, ec, ea, fb, fc, fa, hb, hc, ha, bb, bc, ba, h0b, h0c, h0a);
        STEP2(ic, ia, ib, ec, ea, eb, fc, fa, fb, hc, ha, hb, bc, ba, bb, h0c, h0a, h0b);
    }
#undef STEP2
}

__device__ __forceinline__ void it2_decode(
    int gw, int& lane_strip, int& chunk, int& z) { }

__global__ void __launch_bounds__(IT2_BLOCK, 6) k_iter2(int flip) {
    const int lane = threadIdx.x & 31;
    const int gw = (blockIdx.x * IT2_BLOCK + threadIdx.x) >> 5;
    const int strip = gw % STRIPS;
    const int t = gw / STRIPS;
    const int chunk = t & (CHUNKS - 1);
    const int z = t / CHUNKS;

    const __half* __restrict__ src = (flip ? g_imgB : g_imgA) + z * HWSZ;
    __half* __restrict__ dst = (flip ? g_imgA : g_imgB) + z * HWSZ;
    __half* __restrict__ skel = g_skel + z * HWSZ;

    const int c0 = strip * 120 - 4 + 4 * lane;
    const int r0 = chunk * CHUNK_ROWS;

    const bool rin = (chunk >= 1) && (chunk <= 30);
    const bool cin = (strip >= 1) && (strip <= 3);
    if (rin) {
        if (cin) it2_core<true, true, false>(src, dst, skel, lane, c0, r0);
        else     it2_core<true, false, false>(src, dst, skel, lane, c0, r0);
    } else {
        if (cin) it2_core<false, true, false>(src, dst, skel, lane, c0, r0);
        else     it2_core<false, false, false>(src, dst, skel, lane, c0, r0);
    }
}

// First launch: open-init (skel0) + iterations 1,2 fused. imgA -> imgB.
__global__ void __launch_bounds__(IT2_BLOCK, 5) k_first() {
    const int lane = threadIdx.x & 31;
    const int gw = (blockIdx.x * IT2_BLOCK + threadIdx.x) >> 5;
    const int strip = gw % STRIPS;
    const int t = gw / STRIPS;
    const int chunk = t & (CHUNKS - 1);
    const int z = t / CHUNKS;

    const __half* __restrict__ src = g_imgA + z * HWSZ;
    __half* __restrict__ dst = g_imgB + z * HWSZ;
    __half* __restrict__ skel = g_skel + z * HWSZ;

    const int c0 = strip * 120 - 4 + 4 * lane;
    const int r0 = chunk * CHUNK_ROWS;

    const bool rin = (chunk >= 1) && (chunk <= 30);
    const bool cin = (strip >= 1) && (strip <= 3);
    if (rin) {
        if (cin) it2_core<true, true, true>(src, dst, skel, lane, c0, r0);
        else     it2_core<true, false, true>(src, dst, skel, lane, c0, r0);
    } else {
        if (cin) it2_core<false, true, true>(src, dst, skel, lane, c0, r0);
        else     it2_core<false, false, true>(src, dst, skel, lane, c0, r0);
    }
}

// ---------------------------------------------------------------------------
// Reductions (sigmoid recomputed inline from output; bitwise-same as before)
// ---------------------------------------------------------------------------
__global__ void k_zero() {
    int t = threadIdx.x;
    if (t < NIMG * 7) ((double*)g_sums)[t] = 0.0;
}

__global__ void k_reduce(const float* __restrict__ outp, const float* __restrict__ tgt) {
    const int n = blockIdx.y;
    const H4* __restrict__ sp = (const H4*)(g_skel + n * HWSZ);
    const H4* __restrict__ sl = (const H4*)(g_skel + (NIMG + n) * HWSZ);
    const float4* __restrict__ oo = (const float4*)(outp + n * HWSZ);
    const float4* __restrict__ tt = (const float4*)(tgt + n * HWSZ);
    const int n4 = HWSZ / 4;

    double a0 = 0, a1 = 0, a2 = 0, a3 = 0, a4 = 0, a5 = 0, a6 = 0;
    for (int i = blockIdx.x * blockDim.x + threadIdx.x; i < n4;
         i += gridDim.x * blockDim.x) {
        H4 s1h = sp[i], s2h = sl[i];
        float2 s1lo = __half22float2(s1h.lo), s1hi = __half22float2(s1h.hi);
        float2 s2lo = __half22float2(s2h.lo), s2hi = __half22float2(s2h.hi);
        float4 o = oo[i], tv = tt[i];
        float4 pv;
        pv.x = 1.0f / (1.0f + expf(-o.x));
        pv.y = 1.0f / (1.0f + expf(-o.y));
        pv.z = 1.0f / (1.0f + expf(-o.z));
        pv.w = 1.0f / (1.0f + expf(-o.w));
        a0 += (double)(s1lo.x * tv.x + s1lo.y * tv.y + s1hi.x * tv.z + s1hi.y * tv.w);
        a1 += (double)(s1lo.x + s1lo.y + s1hi.x + s1hi.y);
        a2 += (double)(s2lo.x * pv.x + s2lo.y * pv.y + s2hi.x * pv.z + s2hi.y * pv.w);
        a3 += (double)(s2lo.x + s2lo.y + s2hi.x + s2hi.y);
        a4 += (double)(pv.x * tv.x + pv.y * tv.y + pv.z * tv.z + pv.w * tv.w);
        a5 += (double)(pv.x + pv.y + pv.z + pv.w);
        a6 += (double)(tv.x + tv.y + tv.z + tv.w);
    }
#pragma unroll
    for (int o = 16; o > 0; o >>= 1) {
        a0 += __shfl_down_sync(0xffffffffu, a0, o);
        a1 += __shfl_down_sync(0xffffffffu, a1, o);
        a2 += __shfl_down_sync(0xffffffffu, a2, o);
        a3 += __shfl_down_sync(0xffffffffu, a3, o);
        a4 += __shfl_down_sync(0xffffffffu, a4, o);
        a5 += __shfl_down_sync(0xffffffffu, a5, o);
        a6 += __shfl_down_sync(0xffffffffu, a6, o);
    }
    if ((threadIdx.x & 31) == 0) {
        atomicAdd(&g_sums[n][0], a0);
        atomicAdd(&g_sums[n][1], a1);
        atomicAdd(&g_sums[n][2], a2);
        atomicAdd(&g_sums[n][3], a3);
        atomicAdd(&g_sums[n][4], a4);
        atomicAdd(&g_sums[n][5], a5);
        atomicAdd(&g_sums[n][6], a6);
    }
}

__global__ void k_final(float* __restrict__ out, int out_size) {
    if (threadIdx.x == 0 && blockIdx.x == 0) {
        const double smooth = 1.0;
        double cl = 0.0, dice = 0.0;
        for (int n = 0; n < NIMG; n++) {
            double A = g_sums[n][0], B = g_sums[n][1], C = g_sums[n][2],
                   D = g_sums[n][3], E = g_sums[n][4], F = g_sums[n][5],
                   G = g_sums[n][6];
            double tprec = (A + smooth) / (B + smooth);
            double tsens = (C + smooth) / (D + smooth);
            cl += 1.0 - 2.0 * tprec * tsens / (tprec + tsens);
            dice += 1.0 - 2.0 * (E + smooth) / (F + G + smooth);
        }
        cl /= NIMG;
        dice /= NIMG;
        float loss = (float)(0.7 * dice + 0.3 * cl);
        for (int i = 0; i < out_size; i++) out[i] = loss;
    }
}

// ---------------------------------------------------------------------------
extern "C" void kernel_launch(void* const* d_in, const int* in_sizes, int n_in,
                              void* d_out, int out_size) {
    const float* output = (const float*)d_in[0];
    const float* target = (const float*)d_in[1];
    float* out = (float*)d_out;

    k_init<<<1024, 256>>>((const float4*)output, (const float4*)target);

    // iterations 1-2 fused with open-init (imgA -> imgB)
    k_first<<<IT2_GRID, IT2_BLOCK>>>();

    // iterations 3..50 = 24 fused-2 launches, alternating B->A / A->B
    for (int j = 1; j < NITER / 2; ++j) {
        k_iter2<<<IT2_GRID, IT2_BLOCK>>>(j & 1);
    }

    k_zero<<<1, 64>>>();
    k_reduce<<<dim3(32, NIMG), 256>>>(output, target);
    k_final<<<1, 32>>>(out, out_size);
}